// round 4
// baseline (speedup 1.0000x reference)
#include <cuda_runtime.h>

#define DD 128
#define NODES_PER_TILE 64
#define E_MAX 800000
#define R_MAX 512
#define SPLIT 8
#define SCHUNK 4096

// packed f32x2 FMA: acc = a*b + acc (per 32-bit lane-pair), sm_100+
#define FMA2(acc, a, b) \
    asm("fma.rn.f32x2 %0, %1, %2, %3;" : "=l"(acc) : "l"(a), "l"(b), "l"(acc))
#define PACK2(dst, v) \
    asm("mov.b64 %0, {%1, %1};" : "=l"(dst) : "f"(v))

// ---- scratch (device globals; no allocation allowed) ----
__device__ int  g_off[R_MAX + 1];     // per-type offsets (exclusive scan)
__device__ int  g_cursor[R_MAX];      // per-type reservation cursors
__device__ int4 g_edges[E_MAX];       // sorted {src, dst, scale_bits, pad}

// ---------------------------------------------------------------------------
// Dense kernel: out[n,:] = h[n,:] @ loop_w + exp(-td[n]*0.1) * (prev[n,:] @ time_w)
// Inner loop uses packed fma.rn.f32x2 (2 fp32 FMA per instruction).
// ---------------------------------------------------------------------------
__global__ __launch_bounds__(256, 2)
void dense_kernel(const float* __restrict__ h,
                  const float* __restrict__ prev,
                  const float* __restrict__ time_diff,
                  const float* __restrict__ loop_w,
                  const float* __restrict__ time_w,
                  float* __restrict__ out, int N)
{
    __shared__ float w1s[16][DD];
    __shared__ float w2s[16][DD];
    __shared__ float hs[16][NODES_PER_TILE];
    __shared__ float ps[16][NODES_PER_TILE];

    const int tid  = threadIdx.x;
    const int colg = tid & 15;     // 16 col groups of 8 cols (4 f32x2 pairs)
    const int nrow = tid >> 4;     // 16 node rows (x4 via stride 16)
    const int tile = blockIdx.x * NODES_PER_TILE;

    // accumulators: [node s][pair p] packed f32x2, 8 cols = 4 pairs, 2 matrices
    unsigned long long a1p[4][4], a2p[4][4];
#pragma unroll
    for (int s = 0; s < 4; s++)
#pragma unroll
        for (int p = 0; p < 4; p++) { a1p[s][p] = 0ull; a2p[s][p] = 0ull; }

    const int stage_n  = tid >> 2;
    const int stage_c4 = tid & 3;
    const int stage_node = tile + stage_n;
    const bool stage_ok = (stage_node < N);

#pragma unroll 1
    for (int kc = 0; kc < 8; kc++) {
        const int k0 = kc * 16;
        __syncthreads();
        // stage weights: 512 float4 per matrix, 256 threads x 2
#pragma unroll
        for (int r = 0; r < 2; r++) {
            int idx = tid + r * 256;
            int kk  = idx >> 5;
            int c4  = idx & 31;
            float4 v1 = ((const float4*)(loop_w + (size_t)(k0 + kk) * DD))[c4];
            float4 v2 = ((const float4*)(time_w + (size_t)(k0 + kk) * DD))[c4];
            ((float4*)&w1s[kk][0])[c4] = v1;
            ((float4*)&w2s[kk][0])[c4] = v2;
        }
        // stage h/prev tile, transposed
        {
            float4 vh = make_float4(0.f, 0.f, 0.f, 0.f);
            float4 vp = make_float4(0.f, 0.f, 0.f, 0.f);
            if (stage_ok) {
                vh = ((const float4*)(h    + (size_t)stage_node * DD + k0))[stage_c4];
                vp = ((const float4*)(prev + (size_t)stage_node * DD + k0))[stage_c4];
            }
            int kk = stage_c4 * 4;
            hs[kk + 0][stage_n] = vh.x; hs[kk + 1][stage_n] = vh.y;
            hs[kk + 2][stage_n] = vh.z; hs[kk + 3][stage_n] = vh.w;
            ps[kk + 0][stage_n] = vp.x; ps[kk + 1][stage_n] = vp.y;
            ps[kk + 2][stage_n] = vp.z; ps[kk + 3][stage_n] = vp.w;
        }
        __syncthreads();

#pragma unroll
        for (int kk = 0; kk < 16; kk++) {
            // 8 weight cols per matrix = 4 packed pairs each
            const ulonglong2 wA = *(const ulonglong2*)&w1s[kk][colg * 8 + 0];
            const ulonglong2 wB = *(const ulonglong2*)&w1s[kk][colg * 8 + 4];
            const ulonglong2 uA = *(const ulonglong2*)&w2s[kk][colg * 8 + 0];
            const ulonglong2 uB = *(const ulonglong2*)&w2s[kk][colg * 8 + 4];
#pragma unroll
            for (int s = 0; s < 4; s++) {
                float hv = hs[kk][nrow + s * 16];
                float pv = ps[kk][nrow + s * 16];
                unsigned long long hp, pp;
                PACK2(hp, hv);
                PACK2(pp, pv);
                FMA2(a1p[s][0], hp, wA.x);
                FMA2(a1p[s][1], hp, wA.y);
                FMA2(a1p[s][2], hp, wB.x);
                FMA2(a1p[s][3], hp, wB.y);
                FMA2(a2p[s][0], pp, uA.x);
                FMA2(a2p[s][1], pp, uA.y);
                FMA2(a2p[s][2], pp, uB.x);
                FMA2(a2p[s][3], pp, uB.y);
            }
        }
    }

    // epilogue: out = a1 + dec * a2 (packed)
#pragma unroll
    for (int s = 0; s < 4; s++) {
        int node = tile + nrow + s * 16;
        if (node >= N) continue;
        float dec = __expf(-__ldg(time_diff + node) * 0.1f);
        unsigned long long dp;
        PACK2(dp, dec);
        unsigned long long r0 = a1p[s][0], r1 = a1p[s][1];
        unsigned long long r2 = a1p[s][2], r3 = a1p[s][3];
        FMA2(r0, dp, a2p[s][0]);
        FMA2(r1, dp, a2p[s][1]);
        FMA2(r2, dp, a2p[s][2]);
        FMA2(r3, dp, a2p[s][3]);
        ulonglong2* op = (ulonglong2*)(out + (size_t)node * DD + colg * 8);
        op[0] = make_ulonglong2(r0, r1);
        op[1] = make_ulonglong2(r2, r3);
    }
}

// ---------------------------------------------------------------------------
// Sort pipeline: counting sort of edges by relation type (R bins).
// ---------------------------------------------------------------------------
__global__ void zero_kernel(int R)
{
    int i = blockIdx.x * blockDim.x + threadIdx.x;
    if (i <= R) g_off[i] = 0;
    if (i < R)  g_cursor[i] = 0;
}

__global__ __launch_bounds__(256)
void hist_kernel(const int* __restrict__ etyp, int E, int R)
{
    __shared__ int lh[R_MAX];
    for (int i = threadIdx.x; i < R; i += blockDim.x) lh[i] = 0;
    __syncthreads();
    for (int e = blockIdx.x * blockDim.x + threadIdx.x; e < E;
         e += gridDim.x * blockDim.x)
        atomicAdd(&lh[__ldg(etyp + e)], 1);
    __syncthreads();
    for (int i = threadIdx.x; i < R; i += blockDim.x) {
        int v = lh[i];
        if (v) atomicAdd(&g_off[i + 1], v);
    }
}

__global__ void scan_kernel(int R)
{
    if (threadIdx.x == 0) {
        int acc = 0;
        for (int i = 1; i <= R; i++) { acc += g_off[i]; g_off[i] = acc; }
    }
}

// Two-level scatter: block = one SCHUNK of edges. smem histogram, one global
// atomic per (block,type) to reserve a range, smem-ranked packed writes.
__global__ __launch_bounds__(256)
void scatter_kernel(const int* __restrict__ esrc,
                    const int* __restrict__ edst,
                    const int* __restrict__ etyp,
                    const float* __restrict__ enorm,
                    const float* __restrict__ nnorm,
                    int E, int R)
{
    __shared__ int lbase[R_MAX];
    __shared__ int lcur[R_MAX];

    const int e0 = blockIdx.x * SCHUNK;
    const int e1 = min(e0 + SCHUNK, E);

    for (int i = threadIdx.x; i < R; i += blockDim.x) {
        lbase[i] = 0;
        lcur[i]  = 0;
    }
    __syncthreads();

    for (int e = e0 + threadIdx.x; e < e1; e += blockDim.x)
        atomicAdd(&lbase[__ldg(etyp + e)], 1);
    __syncthreads();

    for (int i = threadIdx.x; i < R; i += blockDim.x) {
        int cnt = lbase[i];
        lbase[i] = cnt ? (g_off[i] + atomicAdd(&g_cursor[i], cnt)) : 0;
    }
    __syncthreads();

    for (int e = e0 + threadIdx.x; e < e1; e += blockDim.x) {
        int t = __ldg(etyp + e);
        int d = __ldg(edst + e);
        int pos = lbase[t] + atomicAdd(&lcur[t], 1);
        float sc = __ldg(enorm + e) * __ldg(nnorm + d);
        g_edges[pos] = make_int4(__ldg(esrc + e), d, __float_as_int(sc), 0);
    }
}

// ---------------------------------------------------------------------------
// Sorted edge kernel: block = (type, chunk). W block in registers per lane.
// Per edge: one int4 metadata load, h[src] float4 gather, 16 FMAs,
// red.global.add.v4 into out (pre-filled with dense part).
// ---------------------------------------------------------------------------
__global__ __launch_bounds__(256)
void edge_sorted_kernel(const float* __restrict__ h,
                        const float* __restrict__ W,
                        float* __restrict__ out)
{
    const int t    = blockIdx.x;
    const int lane = threadIdx.x & 31;
    const int warp = threadIdx.x >> 5;

    const int start = g_off[t];
    const int end   = g_off[t + 1];
    if (start >= end) return;

    const float4* wp = (const float4*)(W + (size_t)t * 512) + lane * 4;
    const float4 w0 = __ldg(wp + 0);
    const float4 w1 = __ldg(wp + 1);
    const float4 w2 = __ldg(wp + 2);
    const float4 w3 = __ldg(wp + 3);

    for (int e = start + blockIdx.y * 8 + warp; e < end; e += 8 * SPLIT) {
        const int4  md = __ldg(g_edges + e);
        const int   s  = md.x;
        const int   d  = md.y;
        const float sc = __int_as_float(md.z);

        float4 hv = __ldg((const float4*)(h + (size_t)s * DD) + lane);

        float4 m;
        m.x = hv.x * w0.x + hv.y * w1.x + hv.z * w2.x + hv.w * w3.x;
        m.y = hv.x * w0.y + hv.y * w1.y + hv.z * w2.y + hv.w * w3.y;
        m.z = hv.x * w0.z + hv.y * w1.z + hv.z * w2.z + hv.w * w3.z;
        m.w = hv.x * w0.w + hv.y * w1.w + hv.z * w2.w + hv.w * w3.w;
        m.x *= sc; m.y *= sc; m.z *= sc; m.w *= sc;

        float* dst = out + (size_t)d * DD + lane * 4;
        asm volatile("red.global.add.v4.f32 [%0], {%1,%2,%3,%4};"
                     :: "l"(dst), "f"(m.x), "f"(m.y), "f"(m.z), "f"(m.w)
                     : "memory");
    }
}

__global__ void relu_kernel(float* __restrict__ x, int n)
{
    int i = blockIdx.x * blockDim.x + threadIdx.x;
    if (i < n) {
        float v = x[i];
        x[i] = v > 0.f ? v : 0.f;
    }
}

extern "C" void kernel_launch(void* const* d_in, const int* in_sizes, int n_in,
                              void* d_out, int out_size)
{
    const float* h   = (const float*)d_in[0];
    const float* fp  = (const float*)d_in[1];
    const float* sp  = (const float*)d_in[2];
    const float* td  = (const float*)d_in[3];
    const int*   es  = (const int*)  d_in[4];
    const int*   ed  = (const int*)  d_in[5];
    const int*   et  = (const int*)  d_in[6];
    const float* en  = (const float*)d_in[7];
    const float* nn  = (const float*)d_in[8];
    const float* W1  = (const float*)d_in[9];
    const float* W2  = (const float*)d_in[10];
    const float* lw1 = (const float*)d_in[11];
    const float* lw2 = (const float*)d_in[12];
    const float* tw1 = (const float*)d_in[13];
    const float* tw2 = (const float*)d_in[14];

    const int N = in_sizes[3];            // time_diff is (N,1)
    const int E = in_sizes[4];            // edge_src is (E,)
    const int R = in_sizes[9] / 512;      // W1 is (R, 512)

    float* h1 = (float*)d_out;
    float* h2 = h1 + (size_t)N * DD;

    const int denseBlocks   = (N + NODES_PER_TILE - 1) / NODES_PER_TILE;
    const int scatterBlocks = (E + SCHUNK - 1) / SCHUNK;
    dim3 edgeGrid(R, SPLIT);

    // ---- sort edges by relation type (once, reused by both layers) ----
    zero_kernel   <<<(R + 256) / 256, 256>>>(R);
    hist_kernel   <<<256, 256>>>(et, E, R);
    scan_kernel   <<<1, 32>>>(R);
    scatter_kernel<<<scatterBlocks, 256>>>(es, ed, et, en, nn, E, R);

    // ---- layer 1 ----
    dense_kernel<<<denseBlocks, 256>>>(h, fp, td, lw1, tw1, h1, N);
    edge_sorted_kernel<<<edgeGrid, 256>>>(h, W1, h1);

    // ---- layer 2 ----
    dense_kernel<<<denseBlocks, 256>>>(h1, sp, td, lw2, tw2, h2, N);
    edge_sorted_kernel<<<edgeGrid, 256>>>(h1, W2, h2);
    relu_kernel<<<((size_t)N * DD + 255) / 256, 256>>>(h2, N * DD);
}

// round 5
// speedup vs baseline: 1.0965x; 1.0965x over previous
#include <cuda_runtime.h>

#define DD 128
#define NODES_PER_TILE 64
#define E_MAX 800000
#define R_MAX 512
#define SPLIT 8
#define SCHUNK 4096

// ---- scratch (device globals; no allocation allowed) ----
__device__ int  g_off[R_MAX + 1];     // per-type offsets (exclusive scan)
__device__ int  g_cursor[R_MAX];      // per-type reservation cursors
__device__ int4 g_edges[E_MAX];       // sorted {src, dst, scale_bits, pad}

// ---------------------------------------------------------------------------
// Dense kernel (R3 FFMA version — known good):
// out[n,:] = h[n,:] @ loop_w + exp(-td[n]*0.1) * (prev[n,:] @ time_w)
// ---------------------------------------------------------------------------
__global__ __launch_bounds__(256, 2)
void dense_kernel(const float* __restrict__ h,
                  const float* __restrict__ prev,
                  const float* __restrict__ time_diff,
                  const float* __restrict__ loop_w,
                  const float* __restrict__ time_w,
                  float* __restrict__ out, int N)
{
    __shared__ float w1s[16][DD];
    __shared__ float w2s[16][DD];
    __shared__ float hs[16][NODES_PER_TILE];
    __shared__ float ps[16][NODES_PER_TILE];

    const int tid  = threadIdx.x;
    const int colg = tid & 15;
    const int nrow = tid >> 4;
    const int tile = blockIdx.x * NODES_PER_TILE;

    float4 a1[4][2];
    float4 a2[4][2];
#pragma unroll
    for (int s = 0; s < 4; s++)
#pragma unroll
        for (int j = 0; j < 2; j++) {
            a1[s][j] = make_float4(0.f, 0.f, 0.f, 0.f);
            a2[s][j] = make_float4(0.f, 0.f, 0.f, 0.f);
        }

    const int stage_n  = tid >> 2;
    const int stage_c4 = tid & 3;
    const int stage_node = tile + stage_n;
    const bool stage_ok = (stage_node < N);

#pragma unroll 1
    for (int kc = 0; kc < 8; kc++) {
        const int k0 = kc * 16;
        __syncthreads();
#pragma unroll
        for (int r = 0; r < 2; r++) {
            int idx = tid + r * 256;
            int kk  = idx >> 5;
            int c4  = idx & 31;
            float4 v1 = ((const float4*)(loop_w + (size_t)(k0 + kk) * DD))[c4];
            float4 v2 = ((const float4*)(time_w + (size_t)(k0 + kk) * DD))[c4];
            ((float4*)&w1s[kk][0])[c4] = v1;
            ((float4*)&w2s[kk][0])[c4] = v2;
        }
        {
            float4 vh = make_float4(0.f, 0.f, 0.f, 0.f);
            float4 vp = make_float4(0.f, 0.f, 0.f, 0.f);
            if (stage_ok) {
                vh = ((const float4*)(h    + (size_t)stage_node * DD + k0))[stage_c4];
                vp = ((const float4*)(prev + (size_t)stage_node * DD + k0))[stage_c4];
            }
            int kk = stage_c4 * 4;
            hs[kk + 0][stage_n] = vh.x; hs[kk + 1][stage_n] = vh.y;
            hs[kk + 2][stage_n] = vh.z; hs[kk + 3][stage_n] = vh.w;
            ps[kk + 0][stage_n] = vp.x; ps[kk + 1][stage_n] = vp.y;
            ps[kk + 2][stage_n] = vp.z; ps[kk + 3][stage_n] = vp.w;
        }
        __syncthreads();

#pragma unroll
        for (int kk = 0; kk < 16; kk++) {
            float4 wa = ((const float4*)&w1s[kk][0])[colg * 2 + 0];
            float4 wb = ((const float4*)&w1s[kk][0])[colg * 2 + 1];
            float4 ua = ((const float4*)&w2s[kk][0])[colg * 2 + 0];
            float4 ub = ((const float4*)&w2s[kk][0])[colg * 2 + 1];
#pragma unroll
            for (int s = 0; s < 4; s++) {
                float hv = hs[kk][nrow + s * 16];
                float pv = ps[kk][nrow + s * 16];
                a1[s][0].x += hv * wa.x; a1[s][0].y += hv * wa.y;
                a1[s][0].z += hv * wa.z; a1[s][0].w += hv * wa.w;
                a1[s][1].x += hv * wb.x; a1[s][1].y += hv * wb.y;
                a1[s][1].z += hv * wb.z; a1[s][1].w += hv * wb.w;
                a2[s][0].x += pv * ua.x; a2[s][0].y += pv * ua.y;
                a2[s][0].z += pv * ua.z; a2[s][0].w += pv * ua.w;
                a2[s][1].x += pv * ub.x; a2[s][1].y += pv * ub.y;
                a2[s][1].z += pv * ub.z; a2[s][1].w += pv * ub.w;
            }
        }
    }

#pragma unroll
    for (int s = 0; s < 4; s++) {
        int node = tile + nrow + s * 16;
        if (node >= N) continue;
        float dec = __expf(-__ldg(time_diff + node) * 0.1f);
        float4 o0, o1;
        o0.x = a1[s][0].x + dec * a2[s][0].x;
        o0.y = a1[s][0].y + dec * a2[s][0].y;
        o0.z = a1[s][0].z + dec * a2[s][0].z;
        o0.w = a1[s][0].w + dec * a2[s][0].w;
        o1.x = a1[s][1].x + dec * a2[s][1].x;
        o1.y = a1[s][1].y + dec * a2[s][1].y;
        o1.z = a1[s][1].z + dec * a2[s][1].z;
        o1.w = a1[s][1].w + dec * a2[s][1].w;
        ((float4*)(out + (size_t)node * DD))[colg * 2 + 0] = o0;
        ((float4*)(out + (size_t)node * DD))[colg * 2 + 1] = o1;
    }
}

// ---------------------------------------------------------------------------
// Sort pipeline: counting sort of edges by relation type (R bins).
// ---------------------------------------------------------------------------
__global__ void zero_kernel(int R)
{
    int i = blockIdx.x * blockDim.x + threadIdx.x;
    if (i <= R) g_off[i] = 0;
    if (i < R)  g_cursor[i] = 0;
}

__global__ __launch_bounds__(256)
void hist_kernel(const int* __restrict__ etyp, int E, int R)
{
    __shared__ int lh[R_MAX];
    for (int i = threadIdx.x; i < R; i += blockDim.x) lh[i] = 0;
    __syncthreads();
    for (int e = blockIdx.x * blockDim.x + threadIdx.x; e < E;
         e += gridDim.x * blockDim.x)
        atomicAdd(&lh[__ldg(etyp + e)], 1);
    __syncthreads();
    for (int i = threadIdx.x; i < R; i += blockDim.x) {
        int v = lh[i];
        if (v) atomicAdd(&g_off[i + 1], v);
    }
}

__global__ void scan_kernel(int R)
{
    if (threadIdx.x == 0) {
        int acc = 0;
        for (int i = 1; i <= R; i++) { acc += g_off[i]; g_off[i] = acc; }
    }
}

// Two-level scatter: smem histogram, one global atomic per (block,type) to
// reserve a range, smem-ranked packed int4 writes.
__global__ __launch_bounds__(256)
void scatter_kernel(const int* __restrict__ esrc,
                    const int* __restrict__ edst,
                    const int* __restrict__ etyp,
                    const float* __restrict__ enorm,
                    const float* __restrict__ nnorm,
                    int E, int R)
{
    __shared__ int lbase[R_MAX];
    __shared__ int lcur[R_MAX];

    const int e0 = blockIdx.x * SCHUNK;
    const int e1 = min(e0 + SCHUNK, E);

    for (int i = threadIdx.x; i < R; i += blockDim.x) {
        lbase[i] = 0;
        lcur[i]  = 0;
    }
    __syncthreads();

    for (int e = e0 + threadIdx.x; e < e1; e += blockDim.x)
        atomicAdd(&lbase[__ldg(etyp + e)], 1);
    __syncthreads();

    for (int i = threadIdx.x; i < R; i += blockDim.x) {
        int cnt = lbase[i];
        lbase[i] = cnt ? (g_off[i] + atomicAdd(&g_cursor[i], cnt)) : 0;
    }
    __syncthreads();

    for (int e = e0 + threadIdx.x; e < e1; e += blockDim.x) {
        int t = __ldg(etyp + e);
        int d = __ldg(edst + e);
        int pos = lbase[t] + atomicAdd(&lcur[t], 1);
        float sc = __ldg(enorm + e) * __ldg(nnorm + d);
        g_edges[pos] = make_int4(__ldg(esrc + e), d, __float_as_int(sc), 0);
    }
}

// ---------------------------------------------------------------------------
// Sorted edge kernel, 2-wide software pipeline: two independent edges per
// loop iteration -> 2 outstanding L2 gathers per warp (double MLP).
// W block in registers per lane (lane = basis index).
// ---------------------------------------------------------------------------
__global__ __launch_bounds__(256)
void edge_sorted_kernel(const float* __restrict__ h,
                        const float* __restrict__ W,
                        float* __restrict__ out)
{
    const int t    = blockIdx.x;
    const int lane = threadIdx.x & 31;
    const int warp = threadIdx.x >> 5;

    const int start = g_off[t];
    const int end   = g_off[t + 1];
    if (start >= end) return;

    const float4* wp = (const float4*)(W + (size_t)t * 512) + lane * 4;
    const float4 w0 = __ldg(wp + 0);
    const float4 w1 = __ldg(wp + 1);
    const float4 w2 = __ldg(wp + 2);
    const float4 w3 = __ldg(wp + 3);

    const int stride = 8 * SPLIT;
    int e = start + blockIdx.y * 8 + warp;

    // 2-wide main loop: edges e and e+stride are independent
    for (; e + stride < end; e += 2 * stride) {
        const int4 mdA = __ldg(g_edges + e);
        const int4 mdB = __ldg(g_edges + e + stride);

        float4 hA = __ldg((const float4*)(h + (size_t)mdA.x * DD) + lane);
        float4 hB = __ldg((const float4*)(h + (size_t)mdB.x * DD) + lane);

        const float scA = __int_as_float(mdA.z);
        const float scB = __int_as_float(mdB.z);

        float4 mA, mB;
        mA.x = hA.x * w0.x + hA.y * w1.x + hA.z * w2.x + hA.w * w3.x;
        mA.y = hA.x * w0.y + hA.y * w1.y + hA.z * w2.y + hA.w * w3.y;
        mA.z = hA.x * w0.z + hA.y * w1.z + hA.z * w2.z + hA.w * w3.z;
        mA.w = hA.x * w0.w + hA.y * w1.w + hA.z * w2.w + hA.w * w3.w;
        mB.x = hB.x * w0.x + hB.y * w1.x + hB.z * w2.x + hB.w * w3.x;
        mB.y = hB.x * w0.y + hB.y * w1.y + hB.z * w2.y + hB.w * w3.y;
        mB.z = hB.x * w0.z + hB.y * w1.z + hB.z * w2.z + hB.w * w3.z;
        mB.w = hB.x * w0.w + hB.y * w1.w + hB.z * w2.w + hB.w * w3.w;
        mA.x *= scA; mA.y *= scA; mA.z *= scA; mA.w *= scA;
        mB.x *= scB; mB.y *= scB; mB.z *= scB; mB.w *= scB;

        float* dA = out + (size_t)mdA.y * DD + lane * 4;
        float* dB = out + (size_t)mdB.y * DD + lane * 4;
        asm volatile("red.global.add.v4.f32 [%0], {%1,%2,%3,%4};"
                     :: "l"(dA), "f"(mA.x), "f"(mA.y), "f"(mA.z), "f"(mA.w)
                     : "memory");
        asm volatile("red.global.add.v4.f32 [%0], {%1,%2,%3,%4};"
                     :: "l"(dB), "f"(mB.x), "f"(mB.y), "f"(mB.z), "f"(mB.w)
                     : "memory");
    }

    // tail (at most one edge left for this warp)
    if (e < end) {
        const int4 md = __ldg(g_edges + e);
        float4 hv = __ldg((const float4*)(h + (size_t)md.x * DD) + lane);
        const float sc = __int_as_float(md.z);

        float4 m;
        m.x = hv.x * w0.x + hv.y * w1.x + hv.z * w2.x + hv.w * w3.x;
        m.y = hv.x * w0.y + hv.y * w1.y + hv.z * w2.y + hv.w * w3.y;
        m.z = hv.x * w0.z + hv.y * w1.z + hv.z * w2.z + hv.w * w3.z;
        m.w = hv.x * w0.w + hv.y * w1.w + hv.z * w2.w + hv.w * w3.w;
        m.x *= sc; m.y *= sc; m.z *= sc; m.w *= sc;

        float* dst = out + (size_t)md.y * DD + lane * 4;
        asm volatile("red.global.add.v4.f32 [%0], {%1,%2,%3,%4};"
                     :: "l"(dst), "f"(m.x), "f"(m.y), "f"(m.z), "f"(m.w)
                     : "memory");
    }
}

__global__ void relu_kernel(float* __restrict__ x, int n)
{
    int i = blockIdx.x * blockDim.x + threadIdx.x;
    if (i < n) {
        float v = x[i];
        x[i] = v > 0.f ? v : 0.f;
    }
}

extern "C" void kernel_launch(void* const* d_in, const int* in_sizes, int n_in,
                              void* d_out, int out_size)
{
    const float* h   = (const float*)d_in[0];
    const float* fp  = (const float*)d_in[1];
    const float* sp  = (const float*)d_in[2];
    const float* td  = (const float*)d_in[3];
    const int*   es  = (const int*)  d_in[4];
    const int*   ed  = (const int*)  d_in[5];
    const int*   et  = (const int*)  d_in[6];
    const float* en  = (const float*)d_in[7];
    const float* nn  = (const float*)d_in[8];
    const float* W1  = (const float*)d_in[9];
    const float* W2  = (const float*)d_in[10];
    const float* lw1 = (const float*)d_in[11];
    const float* lw2 = (const float*)d_in[12];
    const float* tw1 = (const float*)d_in[13];
    const float* tw2 = (const float*)d_in[14];

    const int N = in_sizes[3];            // time_diff is (N,1)
    const int E = in_sizes[4];            // edge_src is (E,)
    const int R = in_sizes[9] / 512;      // W1 is (R, 512)

    float* h1 = (float*)d_out;
    float* h2 = h1 + (size_t)N * DD;

    const int denseBlocks   = (N + NODES_PER_TILE - 1) / NODES_PER_TILE;
    const int scatterBlocks = (E + SCHUNK - 1) / SCHUNK;
    dim3 edgeGrid(R, SPLIT);

    // ---- sort edges by relation type (once, reused by both layers) ----
    zero_kernel   <<<(R + 256) / 256, 256>>>(R);
    hist_kernel   <<<256, 256>>>(et, E, R);
    scan_kernel   <<<1, 32>>>(R);
    scatter_kernel<<<scatterBlocks, 256>>>(es, ed, et, en, nn, E, R);

    // ---- layer 1 ----
    dense_kernel<<<denseBlocks, 256>>>(h, fp, td, lw1, tw1, h1, N);
    edge_sorted_kernel<<<edgeGrid, 256>>>(h, W1, h1);

    // ---- layer 2 ----
    dense_kernel<<<denseBlocks, 256>>>(h1, sp, td, lw2, tw2, h2, N);
    edge_sorted_kernel<<<edgeGrid, 256>>>(h1, W2, h2);
    relu_kernel<<<((size_t)N * DD + 255) / 256, 256>>>(h2, N * DD);
}